// round 1
// baseline (speedup 1.0000x reference)
#include <cuda_runtime.h>
#include <cstdint>

// Problem constants
#define BATCH 4
#define SEQ   2048
#define DMODEL 2048
#define NHEADS 16
#define HDIM  128
#define M_TOK (BATCH * SEQ)          // 8192
#define ATT_SCALE 0.08838834764831845f  // 1/sqrt(128)

// ---------------------------------------------------------------------------
// Scratch: Q,K,V in [B,H,S,Dh] layout, attn output merged [B,S,D]
// (static __device__ arrays: allocation-guard compliant)
// ---------------------------------------------------------------------------
__device__ float g_q[M_TOK * DMODEL];
__device__ float g_k[M_TOK * DMODEL];
__device__ float g_v[M_TOK * DMODEL];
__device__ float g_attn[M_TOK * DMODEL];

// ---------------------------------------------------------------------------
// GEMM: C[M=8192, N=2048] = A[M,2048] @ W[2048, N] + bias
// mode 0: plain row-major store into dst [M,N]
// mode 1: split-head store into dst [B,H,S,Dh]
// Tile: 128x128x8, 256 threads, 8x8 micro-tile.
// ---------------------------------------------------------------------------
#define GK DMODEL
#define GN DMODEL

__global__ __launch_bounds__(256, 2)
void gemm_kernel(const float* __restrict__ A,
                 const float* __restrict__ W,
                 const float* __restrict__ bias,
                 float* __restrict__ dst,
                 int mode)
{
    __shared__ float sA[8][128];   // transposed: sA[k][m]
    __shared__ float sB[8][128];   // sB[k][n]

    const int tid = threadIdx.x;
    const int bm = blockIdx.y * 128;
    const int bn = blockIdx.x * 128;

    const int tx = tid & 15;       // n dir
    const int ty = tid >> 4;       // m dir
    const int m0 = ty * 8;
    const int n0 = tx * 8;

    float acc[8][8];
#pragma unroll
    for (int i = 0; i < 8; i++)
#pragma unroll
        for (int j = 0; j < 8; j++) acc[i][j] = 0.f;

    // loader assignments
    const int a_r  = tid >> 1;           // 0..127
    const int a_k4 = (tid & 1) * 4;      // 0 or 4
    const int b_k  = tid >> 5;           // 0..7
    const int b_c4 = (tid & 31) * 4;     // 0..124

    const float* Aptr = A + (size_t)(bm + a_r) * GK + a_k4;
    const float* Wptr = W + (size_t)b_k * GN + bn + b_c4;

    for (int k0 = 0; k0 < GK; k0 += 8) {
        float4 av = *(const float4*)(Aptr + k0);
        float4 bv = *(const float4*)(Wptr + (size_t)k0 * GN);

        __syncthreads();   // previous compute done before overwrite
        sA[a_k4 + 0][a_r] = av.x;
        sA[a_k4 + 1][a_r] = av.y;
        sA[a_k4 + 2][a_r] = av.z;
        sA[a_k4 + 3][a_r] = av.w;
        *(float4*)&sB[b_k][b_c4] = bv;
        __syncthreads();

#pragma unroll
        for (int kk = 0; kk < 8; kk++) {
            float4 a0 = *(float4*)&sA[kk][m0];
            float4 a1 = *(float4*)&sA[kk][m0 + 4];
            float4 b0 = *(float4*)&sB[kk][n0];
            float4 b1 = *(float4*)&sB[kk][n0 + 4];
            float a[8] = {a0.x, a0.y, a0.z, a0.w, a1.x, a1.y, a1.z, a1.w};
            float b[8] = {b0.x, b0.y, b0.z, b0.w, b1.x, b1.y, b1.z, b1.w};
#pragma unroll
            for (int i = 0; i < 8; i++)
#pragma unroll
                for (int j = 0; j < 8; j++)
                    acc[i][j] += a[i] * b[j];
        }
    }

    // epilogue
#pragma unroll
    for (int i = 0; i < 8; i++) {
        int row = bm + m0 + i;
#pragma unroll
        for (int jj = 0; jj < 8; jj += 4) {
            int col = bn + n0 + jj;
            float4 bb = *(const float4*)&bias[col];
            float4 v;
            v.x = acc[i][jj + 0] + bb.x;
            v.y = acc[i][jj + 1] + bb.y;
            v.z = acc[i][jj + 2] + bb.z;
            v.w = acc[i][jj + 3] + bb.w;
            if (mode == 0) {
                *(float4*)&dst[(size_t)row * GN + col] = v;
            } else {
                int b_ = row >> 11;        // / SEQ
                int s_ = row & 2047;
                int h_ = col >> 7;         // / HDIM
                int d_ = col & 127;
                *(float4*)&dst[(((size_t)(b_ * NHEADS + h_)) * SEQ + s_) * HDIM + d_] = v;
            }
        }
    }
}

// ---------------------------------------------------------------------------
// Flash attention, fp32, causal. One CTA handles a 64-row Q block of one (b,h).
// BM=BN=64, Dh=128, 256 threads.
//   S-phase micro-tile: 4x4 per thread (tx->4 k-cols, ty->4 q-rows)
//   PV-phase micro-tile: 4 rows x 8 dh-cols per thread
// Q,K stored transposed in smem (stride 68) for conflict-free float4 loads.
// ---------------------------------------------------------------------------
#define BMQ 64
#define BNK 64
#define TSTRIDE 68    // padded stride for transposed tiles and P
// smem floats: sQt 128*68 + sKt 128*68 + sV 64*128 + sP 64*68
#define SM_QT   0
#define SM_KT   (128 * TSTRIDE)
#define SM_V    (2 * 128 * TSTRIDE)
#define SM_P    (2 * 128 * TSTRIDE + BNK * HDIM)
#define SM_FLOATS (2 * 128 * TSTRIDE + BNK * HDIM + BMQ * TSTRIDE)
#define SM_BYTES (SM_FLOATS * 4)

__global__ __launch_bounds__(256, 1)
void attn_kernel(const float* __restrict__ Q,
                 const float* __restrict__ K,
                 const float* __restrict__ V,
                 float* __restrict__ O)
{
    extern __shared__ float sm[];
    float* sQt = sm + SM_QT;
    float* sKt = sm + SM_KT;
    float* sV  = sm + SM_V;
    float* sP  = sm + SM_P;

    const int tid = threadIdx.x;
    const int qb = blockIdx.x;
    const int h  = blockIdx.y;
    const int b  = blockIdx.z;

    const size_t head_off = ((size_t)(b * NHEADS + h)) * SEQ * HDIM;
    const float* Qb = Q + head_off;
    const float* Kb = K + head_off;
    const float* Vb = V + head_off;

    // ---- load Q tile (64 x 128) transposed into sQt[d][r] ----
    for (int i = tid; i < BMQ * 32; i += 256) {
        int c4 = (i & 7) + ((i >> 9) << 3);   // 0..31
        int r  = (i >> 3) & 63;
        float4 v = *(const float4*)(Qb + (size_t)(qb * BMQ + r) * HDIM + c4 * 4);
        sQt[(c4 * 4 + 0) * TSTRIDE + r] = v.x;
        sQt[(c4 * 4 + 1) * TSTRIDE + r] = v.y;
        sQt[(c4 * 4 + 2) * TSTRIDE + r] = v.z;
        sQt[(c4 * 4 + 3) * TSTRIDE + r] = v.w;
    }

    const int tx = tid & 15;
    const int ty = tid >> 4;
    const int r0  = ty * 4;    // q rows
    const int c0  = tx * 4;    // k cols (score)
    const int cc0 = tx * 8;    // dh cols (output)

    float m_i[4], l_i[4], acc[4][8];
#pragma unroll
    for (int i = 0; i < 4; i++) {
        m_i[i] = -1e30f;
        l_i[i] = 0.f;
#pragma unroll
        for (int j = 0; j < 8; j++) acc[i][j] = 0.f;
    }

    __syncthreads();

    for (int kb = 0; kb <= qb; kb++) {
        // ---- load K tile transposed, V tile row-major ----
        for (int i = tid; i < BNK * 32; i += 256) {
            int c4 = (i & 7) + ((i >> 9) << 3);
            int r  = (i >> 3) & 63;
            float4 v = *(const float4*)(Kb + (size_t)(kb * BNK + r) * HDIM + c4 * 4);
            sKt[(c4 * 4 + 0) * TSTRIDE + r] = v.x;
            sKt[(c4 * 4 + 1) * TSTRIDE + r] = v.y;
            sKt[(c4 * 4 + 2) * TSTRIDE + r] = v.z;
            sKt[(c4 * 4 + 3) * TSTRIDE + r] = v.w;
        }
        for (int i = tid; i < BNK * 32; i += 256) {
            int r  = i >> 5;
            int c4 = i & 31;
            *(float4*)&sV[r * HDIM + c4 * 4] =
                *(const float4*)(Vb + (size_t)(kb * BNK + r) * HDIM + c4 * 4);
        }
        __syncthreads();

        // ---- S = Q K^T  (4x4 per thread) ----
        float s[4][4];
#pragma unroll
        for (int i = 0; i < 4; i++)
#pragma unroll
            for (int j = 0; j < 4; j++) s[i][j] = 0.f;

#pragma unroll 4
        for (int d = 0; d < HDIM; d++) {
            float4 q4 = *(float4*)&sQt[d * TSTRIDE + r0];
            float4 k4 = *(float4*)&sKt[d * TSTRIDE + c0];
            float qa[4] = {q4.x, q4.y, q4.z, q4.w};
            float ka[4] = {k4.x, k4.y, k4.z, k4.w};
#pragma unroll
            for (int i = 0; i < 4; i++)
#pragma unroll
                for (int j = 0; j < 4; j++)
                    s[i][j] += qa[i] * ka[j];
        }

        // scale + causal mask (only diagonal block needs masking)
        if (kb == qb) {
#pragma unroll
            for (int i = 0; i < 4; i++)
#pragma unroll
                for (int j = 0; j < 4; j++) {
                    float val = s[i][j] * ATT_SCALE;
                    if ((c0 + j) > (r0 + i)) val = -1e30f;
                    s[i][j] = val;
                }
        } else {
#pragma unroll
            for (int i = 0; i < 4; i++)
#pragma unroll
                for (int j = 0; j < 4; j++) s[i][j] *= ATT_SCALE;
        }

        // ---- online softmax update (per q row) ----
#pragma unroll
        for (int i = 0; i < 4; i++) {
            float mx = fmaxf(fmaxf(s[i][0], s[i][1]), fmaxf(s[i][2], s[i][3]));
#pragma unroll
            for (int o = 8; o > 0; o >>= 1)
                mx = fmaxf(mx, __shfl_xor_sync(0xffffffffu, mx, o));
            float m_new = fmaxf(m_i[i], mx);
            float alpha = __expf(m_i[i] - m_new);
            float sum = 0.f;
#pragma unroll
            for (int j = 0; j < 4; j++) {
                s[i][j] = __expf(s[i][j] - m_new);
                sum += s[i][j];
            }
#pragma unroll
            for (int o = 8; o > 0; o >>= 1)
                sum += __shfl_xor_sync(0xffffffffu, sum, o);
            l_i[i] = l_i[i] * alpha + sum;
            m_i[i] = m_new;
#pragma unroll
            for (int j = 0; j < 8; j++) acc[i][j] *= alpha;
        }

        // ---- write P tile ----
#pragma unroll
        for (int i = 0; i < 4; i++)
#pragma unroll
            for (int j = 0; j < 4; j++)
                sP[(r0 + i) * TSTRIDE + c0 + j] = s[i][j];
        __syncthreads();

        // ---- O += P @ V  (4x8 per thread, k-unroll 4) ----
        for (int k = 0; k < BNK; k += 4) {
            float4 p0 = *(float4*)&sP[(r0 + 0) * TSTRIDE + k];
            float4 p1 = *(float4*)&sP[(r0 + 1) * TSTRIDE + k];
            float4 p2 = *(float4*)&sP[(r0 + 2) * TSTRIDE + k];
            float4 p3 = *(float4*)&sP[(r0 + 3) * TSTRIDE + k];
            float pr[4][4] = {{p0.x, p0.y, p0.z, p0.w},
                              {p1.x, p1.y, p1.z, p1.w},
                              {p2.x, p2.y, p2.z, p2.w},
                              {p3.x, p3.y, p3.z, p3.w}};
#pragma unroll
            for (int t = 0; t < 4; t++) {
                float4 va = *(float4*)&sV[(k + t) * HDIM + cc0];
                float4 vb = *(float4*)&sV[(k + t) * HDIM + cc0 + 4];
                float vv[8] = {va.x, va.y, va.z, va.w, vb.x, vb.y, vb.z, vb.w};
#pragma unroll
                for (int i = 0; i < 4; i++) {
                    float p = pr[i][t];
#pragma unroll
                    for (int j = 0; j < 8; j++)
                        acc[i][j] += p * vv[j];
                }
            }
        }
        __syncthreads();   // before next tile overwrites sKt/sV
    }

    // ---- epilogue: normalize, write merged-head layout [B,S,D] ----
#pragma unroll
    for (int i = 0; i < 4; i++) {
        float inv = 1.f / l_i[i];
        int sg = qb * BMQ + r0 + i;
        size_t base = ((size_t)b * SEQ + sg) * DMODEL + h * HDIM + cc0;
        float4 o0, o1;
        o0.x = acc[i][0] * inv; o0.y = acc[i][1] * inv;
        o0.z = acc[i][2] * inv; o0.w = acc[i][3] * inv;
        o1.x = acc[i][4] * inv; o1.y = acc[i][5] * inv;
        o1.z = acc[i][6] * inv; o1.w = acc[i][7] * inv;
        *(float4*)&O[base]     = o0;
        *(float4*)&O[base + 4] = o1;
    }
}

// ---------------------------------------------------------------------------
// Launch
// ---------------------------------------------------------------------------
extern "C" void kernel_launch(void* const* d_in, const int* in_sizes, int n_in,
                              void* d_out, int out_size)
{
    const float* x  = (const float*)d_in[0];
    const float* Wq = (const float*)d_in[1];
    const float* bq = (const float*)d_in[2];
    const float* Wk = (const float*)d_in[3];
    const float* bk = (const float*)d_in[4];
    const float* Wv = (const float*)d_in[5];
    const float* bv = (const float*)d_in[6];
    const float* Wo = (const float*)d_in[7];
    const float* bo = (const float*)d_in[8];
    float* out = (float*)d_out;

    float *q, *k, *v, *attn;
    cudaGetSymbolAddress((void**)&q,    g_q);
    cudaGetSymbolAddress((void**)&k,    g_k);
    cudaGetSymbolAddress((void**)&v,    g_v);
    cudaGetSymbolAddress((void**)&attn, g_attn);

    cudaFuncSetAttribute(attn_kernel,
                         cudaFuncAttributeMaxDynamicSharedMemorySize, SM_BYTES);

    dim3 gemm_grid(GN / 128, M_TOK / 128);   // (16, 64)

    gemm_kernel<<<gemm_grid, 256>>>(x, Wq, bq, q, 1);
    gemm_kernel<<<gemm_grid, 256>>>(x, Wk, bk, k, 1);
    gemm_kernel<<<gemm_grid, 256>>>(x, Wv, bv, v, 1);

    attn_kernel<<<dim3(SEQ / BMQ, NHEADS, BATCH), 256, SM_BYTES>>>(q, k, v, attn);

    gemm_kernel<<<gemm_grid, 256>>>(attn, Wo, bo, out, 0);
}

// round 2
// speedup vs baseline: 1.8601x; 1.8601x over previous
#include <cuda_runtime.h>
#include <cstdint>

// Problem constants
#define BATCH 4
#define SEQ   2048
#define DMODEL 2048
#define NHEADS 16
#define HDIM  128
#define M_TOK (BATCH * SEQ)          // 8192
#define ATT_SCALE 0.08838834764831845f  // 1/sqrt(128)

// ---------------------------------------------------------------------------
// Scratch: Q,K,V in [B,H,S,Dh] layout, attn output merged [B,S,D]
// ---------------------------------------------------------------------------
__device__ float g_q[M_TOK * DMODEL];
__device__ float g_k[M_TOK * DMODEL];
__device__ float g_v[M_TOK * DMODEL];
__device__ float g_attn[M_TOK * DMODEL];

// ---------------------------------------------------------------------------
// TF32 tensor-core GEMM: C[M=8192, N=2048] = A[M,2048] @ W[2048, N] + bias
// CTA tile 128x128, Ktile 16, 8 warps (2x4), warp tile 64x32.
// mma.sync.aligned.m16n8k8.row.col.f32.tf32.tf32.f32
// smem strides chosen conflict-free for the fragment load patterns:
//   sA [m][k] stride 20: frag banks (20g+t)&31 distinct over g=0..7,t=0..3
//   sB [k][n] stride 136: frag banks (8t+g)&31 distinct
// ---------------------------------------------------------------------------
#define GK DMODEL
#define GN DMODEL
#define SA_ST 20
#define SB_ST 136

__device__ __forceinline__ uint32_t f2tf32(float f) {
    uint32_t r;
    asm("cvt.rna.tf32.f32 %0, %1;" : "=r"(r) : "f"(f));
    return r;
}

__device__ __forceinline__ void mma_tf32(float c[4], const uint32_t a[4], const uint32_t b[2]) {
    asm volatile(
        "mma.sync.aligned.m16n8k8.row.col.f32.tf32.tf32.f32 "
        "{%0,%1,%2,%3}, {%4,%5,%6,%7}, {%8,%9}, {%0,%1,%2,%3};"
        : "+f"(c[0]), "+f"(c[1]), "+f"(c[2]), "+f"(c[3])
        : "r"(a[0]), "r"(a[1]), "r"(a[2]), "r"(a[3]), "r"(b[0]), "r"(b[1]));
}

__global__ __launch_bounds__(256, 2)
void gemm_tf32_kernel(const float* __restrict__ A,
                      const float* __restrict__ W,
                      const float* __restrict__ bias,
                      float* __restrict__ dst,
                      int mode)
{
    __shared__ uint32_t sA[2][128 * SA_ST];
    __shared__ uint32_t sB[2][16 * SB_ST];

    const int tid  = threadIdx.x;
    const int wid  = tid >> 5;
    const int lane = tid & 31;
    const int g    = lane >> 2;    // groupID 0..7
    const int t    = lane & 3;     // threadID_in_group 0..3

    const int bm = blockIdx.y * 128;
    const int bn = blockIdx.x * 128;

    const int warp_m = (wid >> 2) * 64;   // 0 or 64
    const int warp_n = (wid & 3) * 32;    // 0,32,64,96

    // loader assignment
    const int a_row = tid >> 1;            // 0..127
    const int a_kc  = (tid & 1) * 4;       // 0 or 4 (plus +8 for second load)
    const int b_row = tid >> 4;            // 0..15
    const int b_col = (tid & 15) * 4;      // 0..60 (plus +64 for second load)

    const float* Aptr = A + (size_t)(bm + a_row) * GK + a_kc;
    const float* Wptr = W + (size_t)b_row * GN + bn + b_col;

    float acc[4][4][4];   // [mfrag][nfrag][4]
#pragma unroll
    for (int i = 0; i < 4; i++)
#pragma unroll
        for (int j = 0; j < 4; j++)
#pragma unroll
            for (int r = 0; r < 4; r++) acc[i][j][r] = 0.f;

    // ---- prologue: load K-tile 0 into buffer 0 ----
    {
        float4 av0 = *(const float4*)(Aptr);
        float4 av1 = *(const float4*)(Aptr + 8);
        float4 bv0 = *(const float4*)(Wptr);
        float4 bv1 = *(const float4*)(Wptr + 64);
        uint32_t* pa = &sA[0][a_row * SA_ST + a_kc];
        pa[0] = f2tf32(av0.x); pa[1] = f2tf32(av0.y);
        pa[2] = f2tf32(av0.z); pa[3] = f2tf32(av0.w);
        pa[8] = f2tf32(av1.x); pa[9] = f2tf32(av1.y);
        pa[10] = f2tf32(av1.z); pa[11] = f2tf32(av1.w);
        uint32_t* pb = &sB[0][b_row * SB_ST + b_col];
        pb[0] = f2tf32(bv0.x); pb[1] = f2tf32(bv0.y);
        pb[2] = f2tf32(bv0.z); pb[3] = f2tf32(bv0.w);
        pb[64] = f2tf32(bv1.x); pb[65] = f2tf32(bv1.y);
        pb[66] = f2tf32(bv1.z); pb[67] = f2tf32(bv1.w);
    }
    __syncthreads();

    for (int k0 = 0; k0 < GK; k0 += 16) {
        const int cur = (k0 >> 4) & 1;
        const bool has_next = (k0 + 16) < GK;

        // prefetch next K-tile into registers
        float4 av0, av1, bv0, bv1;
        if (has_next) {
            av0 = *(const float4*)(Aptr + k0 + 16);
            av1 = *(const float4*)(Aptr + k0 + 24);
            bv0 = *(const float4*)(Wptr + (size_t)(k0 + 16) * GN);
            bv1 = *(const float4*)(Wptr + (size_t)(k0 + 16) * GN + 64);
        }

        // compute on current buffer: two k8 sub-steps
        const uint32_t* cA = sA[cur];
        const uint32_t* cB = sB[cur];
#pragma unroll
        for (int kk = 0; kk < 16; kk += 8) {
            uint32_t afr[4][4];
            uint32_t bfr[4][2];
#pragma unroll
            for (int mf = 0; mf < 4; mf++) {
                const int m = warp_m + 16 * mf + g;
                afr[mf][0] = cA[(m)     * SA_ST + kk + t];
                afr[mf][1] = cA[(m + 8) * SA_ST + kk + t];
                afr[mf][2] = cA[(m)     * SA_ST + kk + t + 4];
                afr[mf][3] = cA[(m + 8) * SA_ST + kk + t + 4];
            }
#pragma unroll
            for (int nf = 0; nf < 4; nf++) {
                const int n = warp_n + 8 * nf + g;
                bfr[nf][0] = cB[(kk + t)     * SB_ST + n];
                bfr[nf][1] = cB[(kk + t + 4) * SB_ST + n];
            }
#pragma unroll
            for (int mf = 0; mf < 4; mf++)
#pragma unroll
                for (int nf = 0; nf < 4; nf++)
                    mma_tf32(acc[mf][nf], afr[mf], bfr[nf]);
        }

        // store prefetched tile into other buffer
        if (has_next) {
            const int nxt = cur ^ 1;
            uint32_t* pa = &sA[nxt][a_row * SA_ST + a_kc];
            pa[0] = f2tf32(av0.x); pa[1] = f2tf32(av0.y);
            pa[2] = f2tf32(av0.z); pa[3] = f2tf32(av0.w);
            pa[8] = f2tf32(av1.x); pa[9] = f2tf32(av1.y);
            pa[10] = f2tf32(av1.z); pa[11] = f2tf32(av1.w);
            uint32_t* pb = &sB[nxt][b_row * SB_ST + b_col];
            pb[0] = f2tf32(bv0.x); pb[1] = f2tf32(bv0.y);
            pb[2] = f2tf32(bv0.z); pb[3] = f2tf32(bv0.w);
            pb[64] = f2tf32(bv1.x); pb[65] = f2tf32(bv1.y);
            pb[66] = f2tf32(bv1.z); pb[67] = f2tf32(bv1.w);
        }
        __syncthreads();
    }

    // ---- epilogue: bias add + store ----
#pragma unroll
    for (int mf = 0; mf < 4; mf++) {
#pragma unroll
        for (int nf = 0; nf < 4; nf++) {
            const int col = bn + warp_n + 8 * nf + 2 * t;
            const float b0 = bias[col];
            const float b1 = bias[col + 1];
#pragma unroll
            for (int half = 0; half < 2; half++) {
                const int row = bm + warp_m + 16 * mf + g + 8 * half;
                float2 v;
                v.x = acc[mf][nf][2 * half + 0] + b0;
                v.y = acc[mf][nf][2 * half + 1] + b1;
                if (mode == 0) {
                    *(float2*)&dst[(size_t)row * GN + col] = v;
                } else {
                    const int b_ = row >> 11;
                    const int s_ = row & 2047;
                    const int h_ = col >> 7;
                    const int d_ = col & 127;
                    *(float2*)&dst[(((size_t)(b_ * NHEADS + h_)) * SEQ + s_) * HDIM + d_] = v;
                }
            }
        }
    }
}

// ---------------------------------------------------------------------------
// Flash attention, fp32, causal (unchanged from round 1).
// ---------------------------------------------------------------------------
#define BMQ 64
#define BNK 64
#define TSTRIDE 68
#define SM_QT   0
#define SM_KT   (128 * TSTRIDE)
#define SM_V    (2 * 128 * TSTRIDE)
#define SM_P    (2 * 128 * TSTRIDE + BNK * HDIM)
#define SM_FLOATS (2 * 128 * TSTRIDE + BNK * HDIM + BMQ * TSTRIDE)
#define SM_BYTES (SM_FLOATS * 4)

__global__ __launch_bounds__(256, 1)
void attn_kernel(const float* __restrict__ Q,
                 const float* __restrict__ K,
                 const float* __restrict__ V,
                 float* __restrict__ O)
{
    extern __shared__ float sm[];
    float* sQt = sm + SM_QT;
    float* sKt = sm + SM_KT;
    float* sV  = sm + SM_V;
    float* sP  = sm + SM_P;

    const int tid = threadIdx.x;
    const int qb = blockIdx.x;
    const int h  = blockIdx.y;
    const int b  = blockIdx.z;

    const size_t head_off = ((size_t)(b * NHEADS + h)) * SEQ * HDIM;
    const float* Qb = Q + head_off;
    const float* Kb = K + head_off;
    const float* Vb = V + head_off;

    for (int i = tid; i < BMQ * 32; i += 256) {
        int c4 = (i & 7) + ((i >> 9) << 3);
        int r  = (i >> 3) & 63;
        float4 v = *(const float4*)(Qb + (size_t)(qb * BMQ + r) * HDIM + c4 * 4);
        sQt[(c4 * 4 + 0) * TSTRIDE + r] = v.x;
        sQt[(c4 * 4 + 1) * TSTRIDE + r] = v.y;
        sQt[(c4 * 4 + 2) * TSTRIDE + r] = v.z;
        sQt[(c4 * 4 + 3) * TSTRIDE + r] = v.w;
    }

    const int tx = tid & 15;
    const int ty = tid >> 4;
    const int r0  = ty * 4;
    const int c0  = tx * 4;
    const int cc0 = tx * 8;

    float m_i[4], l_i[4], acc[4][8];
#pragma unroll
    for (int i = 0; i < 4; i++) {
        m_i[i] = -1e30f;
        l_i[i] = 0.f;
#pragma unroll
        for (int j = 0; j < 8; j++) acc[i][j] = 0.f;
    }

    __syncthreads();

    for (int kb = 0; kb <= qb; kb++) {
        for (int i = tid; i < BNK * 32; i += 256) {
            int c4 = (i & 7) + ((i >> 9) << 3);
            int r  = (i >> 3) & 63;
            float4 v = *(const float4*)(Kb + (size_t)(kb * BNK + r) * HDIM + c4 * 4);
            sKt[(c4 * 4 + 0) * TSTRIDE + r] = v.x;
            sKt[(c4 * 4 + 1) * TSTRIDE + r] = v.y;
            sKt[(c4 * 4 + 2) * TSTRIDE + r] = v.z;
            sKt[(c4 * 4 + 3) * TSTRIDE + r] = v.w;
        }
        for (int i = tid; i < BNK * 32; i += 256) {
            int r  = i >> 5;
            int c4 = i & 31;
            *(float4*)&sV[r * HDIM + c4 * 4] =
                *(const float4*)(Vb + (size_t)(kb * BNK + r) * HDIM + c4 * 4);
        }
        __syncthreads();

        float s[4][4];
#pragma unroll
        for (int i = 0; i < 4; i++)
#pragma unroll
            for (int j = 0; j < 4; j++) s[i][j] = 0.f;

#pragma unroll 4
        for (int d = 0; d < HDIM; d++) {
            float4 q4 = *(float4*)&sQt[d * TSTRIDE + r0];
            float4 k4 = *(float4*)&sKt[d * TSTRIDE + c0];
            float qa[4] = {q4.x, q4.y, q4.z, q4.w};
            float ka[4] = {k4.x, k4.y, k4.z, k4.w};
#pragma unroll
            for (int i = 0; i < 4; i++)
#pragma unroll
                for (int j = 0; j < 4; j++)
                    s[i][j] += qa[i] * ka[j];
        }

        if (kb == qb) {
#pragma unroll
            for (int i = 0; i < 4; i++)
#pragma unroll
                for (int j = 0; j < 4; j++) {
                    float val = s[i][j] * ATT_SCALE;
                    if ((c0 + j) > (r0 + i)) val = -1e30f;
                    s[i][j] = val;
                }
        } else {
#pragma unroll
            for (int i = 0; i < 4; i++)
#pragma unroll
                for (int j = 0; j < 4; j++) s[i][j] *= ATT_SCALE;
        }

#pragma unroll
        for (int i = 0; i < 4; i++) {
            float mx = fmaxf(fmaxf(s[i][0], s[i][1]), fmaxf(s[i][2], s[i][3]));
#pragma unroll
            for (int o = 8; o > 0; o >>= 1)
                mx = fmaxf(mx, __shfl_xor_sync(0xffffffffu, mx, o));
            float m_new = fmaxf(m_i[i], mx);
            float alpha = __expf(m_i[i] - m_new);
            float sum = 0.f;
#pragma unroll
            for (int j = 0; j < 4; j++) {
                s[i][j] = __expf(s[i][j] - m_new);
                sum += s[i][j];
            }
#pragma unroll
            for (int o = 8; o > 0; o >>= 1)
                sum += __shfl_xor_sync(0xffffffffu, sum, o);
            l_i[i] = l_i[i] * alpha + sum;
            m_i[i] = m_new;
#pragma unroll
            for (int j = 0; j < 8; j++) acc[i][j] *= alpha;
        }

#pragma unroll
        for (int i = 0; i < 4; i++)
#pragma unroll
            for (int j = 0; j < 4; j++)
                sP[(r0 + i) * TSTRIDE + c0 + j] = s[i][j];
        __syncthreads();

        for (int k = 0; k < BNK; k += 4) {
            float4 p0 = *(float4*)&sP[(r0 + 0) * TSTRIDE + k];
            float4 p1 = *(float4*)&sP[(r0 + 1) * TSTRIDE + k];
            float4 p2 = *(float4*)&sP[(r0 + 2) * TSTRIDE + k];
            float4 p3 = *(float4*)&sP[(r0 + 3) * TSTRIDE + k];
            float pr[4][4] = {{p0.x, p0.y, p0.z, p0.w},
                              {p1.x, p1.y, p1.z, p1.w},
                              {p2.x, p2.y, p2.z, p2.w},
                              {p3.x, p3.y, p3.z, p3.w}};
#pragma unroll
            for (int t = 0; t < 4; t++) {
                float4 va = *(float4*)&sV[(k + t) * HDIM + cc0];
                float4 vb = *(float4*)&sV[(k + t) * HDIM + cc0 + 4];
                float vv[8] = {va.x, va.y, va.z, va.w, vb.x, vb.y, vb.z, vb.w};
#pragma unroll
                for (int i = 0; i < 4; i++) {
                    float p = pr[i][t];
#pragma unroll
                    for (int j = 0; j < 8; j++)
                        acc[i][j] += p * vv[j];
                }
            }
        }
        __syncthreads();
    }

#pragma unroll
    for (int i = 0; i < 4; i++) {
        float inv = 1.f / l_i[i];
        int sg = qb * BMQ + r0 + i;
        size_t base = ((size_t)b * SEQ + sg) * DMODEL + h * HDIM + cc0;
        float4 o0, o1;
        o0.x = acc[i][0] * inv; o0.y = acc[i][1] * inv;
        o0.z = acc[i][2] * inv; o0.w = acc[i][3] * inv;
        o1.x = acc[i][4] * inv; o1.y = acc[i][5] * inv;
        o1.z = acc[i][6] * inv; o1.w = acc[i][7] * inv;
        *(float4*)&O[base]     = o0;
        *(float4*)&O[base + 4] = o1;
    }
}

// ---------------------------------------------------------------------------
// Launch
// ---------------------------------------------------------------------------
extern "C" void kernel_launch(void* const* d_in, const int* in_sizes, int n_in,
                              void* d_out, int out_size)
{
    const float* x  = (const float*)d_in[0];
    const float* Wq = (const float*)d_in[1];
    const float* bq = (const float*)d_in[2];
    const float* Wk = (const float*)d_in[3];
    const float* bk = (const float*)d_in[4];
    const float* Wv = (const float*)d_in[5];
    const float* bv = (const float*)d_in[6];
    const float* Wo = (const float*)d_in[7];
    const float* bo = (const float*)d_in[8];
    float* out = (float*)d_out;

    float *q, *k, *v, *attn;
    cudaGetSymbolAddress((void**)&q,    g_q);
    cudaGetSymbolAddress((void**)&k,    g_k);
    cudaGetSymbolAddress((void**)&v,    g_v);
    cudaGetSymbolAddress((void**)&attn, g_attn);

    cudaFuncSetAttribute(attn_kernel,
                         cudaFuncAttributeMaxDynamicSharedMemorySize, SM_BYTES);

    dim3 gemm_grid(GN / 128, M_TOK / 128);   // (16, 64)

    gemm_tf32_kernel<<<gemm_grid, 256>>>(x, Wq, bq, q, 1);
    gemm_tf32_kernel<<<gemm_grid, 256>>>(x, Wk, bk, k, 1);
    gemm_tf32_kernel<<<gemm_grid, 256>>>(x, Wv, bv, v, 1);

    attn_kernel<<<dim3(SEQ / BMQ, NHEADS, BATCH), 256, SM_BYTES>>>(q, k, v, attn);

    gemm_tf32_kernel<<<gemm_grid, 256>>>(attn, Wo, bo, out, 0);
}

// round 3
// speedup vs baseline: 3.1496x; 1.6933x over previous
#include <cuda_runtime.h>
#include <cstdint>

// Problem constants
#define BATCH 4
#define SEQ   2048
#define DMODEL 2048
#define NHEADS 16
#define HDIM  128
#define M_TOK (BATCH * SEQ)          // 8192
// softmax scale folded with log2(e):  (1/sqrt(128)) * log2(e)
#define SL2 (0.08838834764831845f * 1.4426950408889634f)

// ---------------------------------------------------------------------------
// Scratch
// ---------------------------------------------------------------------------
__device__ float g_q[M_TOK * DMODEL];
__device__ float g_k[M_TOK * DMODEL];
__device__ float g_v[M_TOK * DMODEL];
__device__ float g_attn[M_TOK * DMODEL];

// ---------------------------------------------------------------------------
// Common PTX helpers
// ---------------------------------------------------------------------------
__device__ __forceinline__ uint32_t f2tf32(float f) {
    uint32_t r;
    asm("cvt.rna.tf32.f32 %0, %1;" : "=r"(r) : "f"(f));
    return r;
}

__device__ __forceinline__ void mma_tf32(float c[4], const uint32_t a[4], const uint32_t b[2]) {
    asm volatile(
        "mma.sync.aligned.m16n8k8.row.col.f32.tf32.tf32.f32 "
        "{%0,%1,%2,%3}, {%4,%5,%6,%7}, {%8,%9}, {%0,%1,%2,%3};"
        : "+f"(c[0]), "+f"(c[1]), "+f"(c[2]), "+f"(c[3])
        : "r"(a[0]), "r"(a[1]), "r"(a[2]), "r"(a[3]), "r"(b[0]), "r"(b[1]));
}

__device__ __forceinline__ float ex2(float x) {
    float y;
    asm("ex2.approx.f32 %0, %1;" : "=f"(y) : "f"(x));
    return y;
}

__device__ __forceinline__ void cp16(float* dst_smem, const float* src_gmem) {
    uint32_t d = (uint32_t)__cvta_generic_to_shared(dst_smem);
    asm volatile("cp.async.cg.shared.global [%0], [%1], 16;" :: "r"(d), "l"(src_gmem));
}
__device__ __forceinline__ void cp_commit() {
    asm volatile("cp.async.commit_group;");
}
template<int N> __device__ __forceinline__ void cp_wait() {
    asm volatile("cp.async.wait_group %0;" :: "n"(N));
}

// ---------------------------------------------------------------------------
// TF32 tensor-core GEMM (unchanged from round 2; known-good)
// ---------------------------------------------------------------------------
#define GK DMODEL
#define GN DMODEL
#define SA_ST 20
#define SB_ST 136

__global__ __launch_bounds__(256, 2)
void gemm_tf32_kernel(const float* __restrict__ A,
                      const float* __restrict__ W,
                      const float* __restrict__ bias,
                      float* __restrict__ dst,
                      int mode)
{
    __shared__ uint32_t sA[2][128 * SA_ST];
    __shared__ uint32_t sB[2][16 * SB_ST];

    const int tid  = threadIdx.x;
    const int wid  = tid >> 5;
    const int lane = tid & 31;
    const int g    = lane >> 2;
    const int t    = lane & 3;

    const int bm = blockIdx.y * 128;
    const int bn = blockIdx.x * 128;

    const int warp_m = (wid >> 2) * 64;
    const int warp_n = (wid & 3) * 32;

    const int a_row = tid >> 1;
    const int a_kc  = (tid & 1) * 4;
    const int b_row = tid >> 4;
    const int b_col = (tid & 15) * 4;

    const float* Aptr = A + (size_t)(bm + a_row) * GK + a_kc;
    const float* Wptr = W + (size_t)b_row * GN + bn + b_col;

    float acc[4][4][4];
#pragma unroll
    for (int i = 0; i < 4; i++)
#pragma unroll
        for (int j = 0; j < 4; j++)
#pragma unroll
            for (int r = 0; r < 4; r++) acc[i][j][r] = 0.f;

    {
        float4 av0 = *(const float4*)(Aptr);
        float4 av1 = *(const float4*)(Aptr + 8);
        float4 bv0 = *(const float4*)(Wptr);
        float4 bv1 = *(const float4*)(Wptr + 64);
        uint32_t* pa = &sA[0][a_row * SA_ST + a_kc];
        pa[0] = f2tf32(av0.x); pa[1] = f2tf32(av0.y);
        pa[2] = f2tf32(av0.z); pa[3] = f2tf32(av0.w);
        pa[8] = f2tf32(av1.x); pa[9] = f2tf32(av1.y);
        pa[10] = f2tf32(av1.z); pa[11] = f2tf32(av1.w);
        uint32_t* pb = &sB[0][b_row * SB_ST + b_col];
        pb[0] = f2tf32(bv0.x); pb[1] = f2tf32(bv0.y);
        pb[2] = f2tf32(bv0.z); pb[3] = f2tf32(bv0.w);
        pb[64] = f2tf32(bv1.x); pb[65] = f2tf32(bv1.y);
        pb[66] = f2tf32(bv1.z); pb[67] = f2tf32(bv1.w);
    }
    __syncthreads();

    for (int k0 = 0; k0 < GK; k0 += 16) {
        const int cur = (k0 >> 4) & 1;
        const bool has_next = (k0 + 16) < GK;

        float4 av0, av1, bv0, bv1;
        if (has_next) {
            av0 = *(const float4*)(Aptr + k0 + 16);
            av1 = *(const float4*)(Aptr + k0 + 24);
            bv0 = *(const float4*)(Wptr + (size_t)(k0 + 16) * GN);
            bv1 = *(const float4*)(Wptr + (size_t)(k0 + 16) * GN + 64);
        }

        const uint32_t* cA = sA[cur];
        const uint32_t* cB = sB[cur];
#pragma unroll
        for (int kk = 0; kk < 16; kk += 8) {
            uint32_t afr[4][4];
            uint32_t bfr[4][2];
#pragma unroll
            for (int mf = 0; mf < 4; mf++) {
                const int m = warp_m + 16 * mf + g;
                afr[mf][0] = cA[(m)     * SA_ST + kk + t];
                afr[mf][1] = cA[(m + 8) * SA_ST + kk + t];
                afr[mf][2] = cA[(m)     * SA_ST + kk + t + 4];
                afr[mf][3] = cA[(m + 8) * SA_ST + kk + t + 4];
            }
#pragma unroll
            for (int nf = 0; nf < 4; nf++) {
                const int n = warp_n + 8 * nf + g;
                bfr[nf][0] = cB[(kk + t)     * SB_ST + n];
                bfr[nf][1] = cB[(kk + t + 4) * SB_ST + n];
            }
#pragma unroll
            for (int mf = 0; mf < 4; mf++)
#pragma unroll
                for (int nf = 0; nf < 4; nf++)
                    mma_tf32(acc[mf][nf], afr[mf], bfr[nf]);
        }

        if (has_next) {
            const int nxt = cur ^ 1;
            uint32_t* pa = &sA[nxt][a_row * SA_ST + a_kc];
            pa[0] = f2tf32(av0.x); pa[1] = f2tf32(av0.y);
            pa[2] = f2tf32(av0.z); pa[3] = f2tf32(av0.w);
            pa[8] = f2tf32(av1.x); pa[9] = f2tf32(av1.y);
            pa[10] = f2tf32(av1.z); pa[11] = f2tf32(av1.w);
            uint32_t* pb = &sB[nxt][b_row * SB_ST + b_col];
            pb[0] = f2tf32(bv0.x); pb[1] = f2tf32(bv0.y);
            pb[2] = f2tf32(bv0.z); pb[3] = f2tf32(bv0.w);
            pb[64] = f2tf32(bv1.x); pb[65] = f2tf32(bv1.y);
            pb[66] = f2tf32(bv1.z); pb[67] = f2tf32(bv1.w);
        }
        __syncthreads();
    }

#pragma unroll
    for (int mf = 0; mf < 4; mf++) {
#pragma unroll
        for (int nf = 0; nf < 4; nf++) {
            const int col = bn + warp_n + 8 * nf + 2 * t;
            const float b0 = bias[col];
            const float b1 = bias[col + 1];
#pragma unroll
            for (int half = 0; half < 2; half++) {
                const int row = bm + warp_m + 16 * mf + g + 8 * half;
                float2 v;
                v.x = acc[mf][nf][2 * half + 0] + b0;
                v.y = acc[mf][nf][2 * half + 1] + b1;
                if (mode == 0) {
                    *(float2*)&dst[(size_t)row * GN + col] = v;
                } else {
                    const int b_ = row >> 11;
                    const int s_ = row & 2047;
                    const int h_ = col >> 7;
                    const int d_ = col & 127;
                    *(float2*)&dst[(((size_t)(b_ * NHEADS + h_)) * SEQ + s_) * HDIM + d_] = v;
                }
            }
        }
    }
}

// ---------------------------------------------------------------------------
// Tensor-core flash attention (tf32 mma), causal.
// BM=128 q rows per CTA, BN=64 kseq per tile, 8 warps, warp w owns q rows
// [16w, 16w+16).  Computes S^T = K @ Q^T so that A (=K) and B (=Qt) layouts
// need no per-tile transpose; P^T is per-warp private.
// smem strides (floats): K 132 (A-frag banks 4g+t), Qt/V/PT 136 (8t+g).
// ---------------------------------------------------------------------------
#define K_ST 132
#define V_ST 136
#define Q_ST 136
#define P_ST 136

#define SM_QT_F   (128 * Q_ST)            // 17408
#define SM_K_F    (2 * 64 * K_ST)         // 16896
#define SM_V_F    (64 * V_ST)             // 8704
#define SM_PT_F   (64 * P_ST)             // 8704
#define SM_RED_F  128
#define SMA_FLOATS (SM_QT_F + SM_K_F + SM_V_F + SM_PT_F + SM_RED_F)
#define SMA_BYTES  (SMA_FLOATS * 4)       // 207872 B

__device__ __forceinline__ void load_k_tile(float* dst, const float* src, int tid) {
#pragma unroll
    for (int j = 0; j < 8; j++) {
        int c = tid + j * 256;
        int row = c >> 5;
        int c16 = (c & 31) * 4;
        cp16(dst + row * K_ST + c16, src + (size_t)row * HDIM + c16);
    }
}
__device__ __forceinline__ void load_v_tile(float* dst, const float* src, int tid) {
#pragma unroll
    for (int j = 0; j < 8; j++) {
        int c = tid + j * 256;
        int row = c >> 5;
        int c16 = (c & 31) * 4;
        cp16(dst + row * V_ST + c16, src + (size_t)row * HDIM + c16);
    }
}

__global__ __launch_bounds__(256, 1)
void attn_mma_kernel(const float* __restrict__ Q,
                     const float* __restrict__ K,
                     const float* __restrict__ V,
                     float* __restrict__ O)
{
    extern __shared__ float sm[];
    float* sQt  = sm;
    float* sK   = sQt + SM_QT_F;
    float* sV   = sK + SM_K_F;
    float* sPT  = sV + SM_V_F;
    float* sRed = sPT + SM_PT_F;

    const int tid  = threadIdx.x;
    const int wid  = tid >> 5;
    const int lane = tid & 31;
    const int g    = lane >> 2;
    const int t    = lane & 3;
    const int qw   = 16 * wid;           // warp's q offset inside CTA

    const int qb = (gridDim.x - 1) - blockIdx.x;   // heavy blocks first
    const int h  = blockIdx.y;
    const int b  = blockIdx.z;

    const size_t head = ((size_t)(b * NHEADS + h)) * SEQ * HDIM;
    const float* Qb = Q + head + (size_t)qb * 128 * HDIM;
    const float* Kb = K + head;
    const float* Vb = V + head;

    // ---- load Q transposed into sQt[d][q], tf32-rounded ----
    for (int i = tid; i < 128 * 32; i += 256) {
        int c4 = i >> 7;          // 0..31 (d/4)
        int q  = i & 127;
        float4 v = *(const float4*)(Qb + (size_t)q * HDIM + c4 * 4);
        sQt[(4 * c4 + 0) * Q_ST + q] = __uint_as_float(f2tf32(v.x));
        sQt[(4 * c4 + 1) * Q_ST + q] = __uint_as_float(f2tf32(v.y));
        sQt[(4 * c4 + 2) * Q_ST + q] = __uint_as_float(f2tf32(v.z));
        sQt[(4 * c4 + 3) * Q_ST + q] = __uint_as_float(f2tf32(v.w));
    }

    const int ntiles = 2 * (qb + 1);

    // prologue: K(0), V(0)
    load_k_tile(sK, Kb, tid);            cp_commit();
    load_v_tile(sV, Vb, tid);            cp_commit();

    float m_i[2][2], l_i[2][2];
    float acc_o[16][4];
#pragma unroll
    for (int nf = 0; nf < 2; nf++)
#pragma unroll
        for (int par = 0; par < 2; par++) { m_i[nf][par] = -1e30f; l_i[nf][par] = 0.f; }
#pragma unroll
    for (int i = 0; i < 16; i++)
#pragma unroll
        for (int r = 0; r < 4; r++) acc_o[i][r] = 0.f;

    __syncthreads();   // sQt visible

    for (int kb = 0; kb < ntiles; kb++) {
        const bool has_next = (kb + 1) < ntiles;
        if (has_next) {
            load_k_tile(sK + ((kb + 1) & 1) * 64 * K_ST,
                        Kb + (size_t)(kb + 1) * 64 * HDIM, tid);
            cp_commit();
        }
        // wait K(kb):   pending allowed = {V(kb), K(kb+1)} or {V(kb)}
        if (has_next) cp_wait<2>(); else cp_wait<1>();
        __syncthreads();

        const float* cK = sK + (kb & 1) * 64 * K_ST;
        // warp-level causal early-out (whole warp's q-slice above diagonal)
        const bool active = (kb * 64) <= (qb * 128 + qw + 15);

        float p[4][2][4];
        if (active) {
#pragma unroll
            for (int mf = 0; mf < 4; mf++)
#pragma unroll
                for (int nf = 0; nf < 2; nf++)
#pragma unroll
                    for (int r = 0; r < 4; r++) p[mf][nf][r] = 0.f;

            // ---- S^T = K @ Q^T ----
#pragma unroll 4
            for (int kk = 0; kk < HDIM; kk += 8) {
                uint32_t afr[4][4];
#pragma unroll
                for (int mf = 0; mf < 4; mf++) {
                    const int m = 16 * mf + g;
                    afr[mf][0] = f2tf32(cK[(m)     * K_ST + kk + t]);
                    afr[mf][1] = f2tf32(cK[(m + 8) * K_ST + kk + t]);
                    afr[mf][2] = f2tf32(cK[(m)     * K_ST + kk + t + 4]);
                    afr[mf][3] = f2tf32(cK[(m + 8) * K_ST + kk + t + 4]);
                }
                uint32_t bfr[2][2];
#pragma unroll
                for (int nf = 0; nf < 2; nf++) {
                    const int qn = qw + 8 * nf + g;
                    bfr[nf][0] = __float_as_uint(sQt[(kk + t)     * Q_ST + qn]);
                    bfr[nf][1] = __float_as_uint(sQt[(kk + t + 4) * Q_ST + qn]);
                }
#pragma unroll
                for (int mf = 0; mf < 4; mf++)
#pragma unroll
                    for (int nf = 0; nf < 2; nf++)
                        mma_tf32(p[mf][nf], afr[mf], bfr[nf]);
            }

            // ---- scale + causal mask ----
            const bool diag = (kb >= ntiles - 2);
            float mx[2][2] = {{-1e30f, -1e30f}, {-1e30f, -1e30f}};
#pragma unroll
            for (int mf = 0; mf < 4; mf++)
#pragma unroll
                for (int nf = 0; nf < 2; nf++) {
                    const int kg = kb * 64 + 16 * mf + g;
                    const int qc = qb * 128 + qw + 8 * nf + 2 * t;
#pragma unroll
                    for (int e = 0; e < 4; e++) {
                        const int kge = kg + ((e >= 2) ? 8 : 0);
                        const int qce = qc + (e & 1);
                        float v = p[mf][nf][e] * SL2;
                        if (diag && kge > qce) v = -1e30f;
                        p[mf][nf][e] = v;
                    }
                    mx[nf][0] = fmaxf(mx[nf][0], fmaxf(p[mf][nf][0], p[mf][nf][2]));
                    mx[nf][1] = fmaxf(mx[nf][1], fmaxf(p[mf][nf][1], p[mf][nf][3]));
                }
            // reduce max over g-lanes (lane = 4g+t)
#pragma unroll
            for (int nf = 0; nf < 2; nf++)
#pragma unroll
                for (int par = 0; par < 2; par++) {
                    float v = mx[nf][par];
                    v = fmaxf(v, __shfl_xor_sync(0xffffffffu, v, 4));
                    v = fmaxf(v, __shfl_xor_sync(0xffffffffu, v, 8));
                    v = fmaxf(v, __shfl_xor_sync(0xffffffffu, v, 16));
                    mx[nf][par] = v;
                }
            float alpha[2][2];
#pragma unroll
            for (int nf = 0; nf < 2; nf++)
#pragma unroll
                for (int par = 0; par < 2; par++) {
                    const float m_new = fmaxf(m_i[nf][par], mx[nf][par]);
                    alpha[nf][par] = ex2(m_i[nf][par] - m_new);
                    m_i[nf][par] = m_new;
                }
            // exp + row sums
            float sum[2][2] = {{0.f, 0.f}, {0.f, 0.f}};
#pragma unroll
            for (int mf = 0; mf < 4; mf++)
#pragma unroll
                for (int nf = 0; nf < 2; nf++) {
                    p[mf][nf][0] = ex2(p[mf][nf][0] - m_i[nf][0]);
                    p[mf][nf][1] = ex2(p[mf][nf][1] - m_i[nf][1]);
                    p[mf][nf][2] = ex2(p[mf][nf][2] - m_i[nf][0]);
                    p[mf][nf][3] = ex2(p[mf][nf][3] - m_i[nf][1]);
                    sum[nf][0] += p[mf][nf][0] + p[mf][nf][2];
                    sum[nf][1] += p[mf][nf][1] + p[mf][nf][3];
                }
#pragma unroll
            for (int nf = 0; nf < 2; nf++)
#pragma unroll
                for (int par = 0; par < 2; par++) {
                    float v = sum[nf][par];
                    v += __shfl_xor_sync(0xffffffffu, v, 4);
                    v += __shfl_xor_sync(0xffffffffu, v, 8);
                    v += __shfl_xor_sync(0xffffffffu, v, 16);
                    l_i[nf][par] = l_i[nf][par] * alpha[nf][par] + v;
                }

            // ---- store P^T (warp-private columns), tf32-rounded ----
#pragma unroll
            for (int mf = 0; mf < 4; mf++)
#pragma unroll
                for (int nf = 0; nf < 2; nf++) {
                    const int kr = 16 * mf + g;
                    const int qc = qw + 8 * nf + 2 * t;
                    sPT[(kr)     * P_ST + qc]     = __uint_as_float(f2tf32(p[mf][nf][0]));
                    sPT[(kr)     * P_ST + qc + 1] = __uint_as_float(f2tf32(p[mf][nf][1]));
                    sPT[(kr + 8) * P_ST + qc]     = __uint_as_float(f2tf32(p[mf][nf][2]));
                    sPT[(kr + 8) * P_ST + qc + 1] = __uint_as_float(f2tf32(p[mf][nf][3]));
                }
            // alpha -> smem strip for O-rescale lane remap
            if (lane < 4) {
#pragma unroll
                for (int nf = 0; nf < 2; nf++)
#pragma unroll
                    for (int par = 0; par < 2; par++)
                        sRed[qw + 8 * nf + 2 * lane + par] = alpha[nf][par];
            }
            __syncwarp();
            const float al0 = sRed[qw + g];
            const float al1 = sRed[qw + g + 8];
#pragma unroll
            for (int nf2 = 0; nf2 < 16; nf2++) {
                acc_o[nf2][0] *= al0; acc_o[nf2][1] *= al0;
                acc_o[nf2][2] *= al1; acc_o[nf2][3] *= al1;
            }
        }

        // wait V(kb): pending allowed = {K(kb+1)} or {}
        if (has_next) cp_wait<1>(); else cp_wait<0>();
        __syncthreads();

        if (active) {
            // ---- O += P @ V ----
#pragma unroll 2
            for (int kk = 0; kk < 64; kk += 8) {
                uint32_t va[4];
                va[0] = __float_as_uint(sPT[(kk + t)     * P_ST + qw + g]);
                va[1] = __float_as_uint(sPT[(kk + t)     * P_ST + qw + g + 8]);
                va[2] = __float_as_uint(sPT[(kk + t + 4) * P_ST + qw + g]);
                va[3] = __float_as_uint(sPT[(kk + t + 4) * P_ST + qw + g + 8]);
#pragma unroll
                for (int nf2 = 0; nf2 < 16; nf2++) {
                    uint32_t vb[2];
                    vb[0] = f2tf32(sV[(kk + t)     * V_ST + 8 * nf2 + g]);
                    vb[1] = f2tf32(sV[(kk + t + 4) * V_ST + 8 * nf2 + g]);
                    mma_tf32(acc_o[nf2], va, vb);
                }
            }
        }

        __syncthreads();   // all warps done reading sV
        if (has_next) {
            load_v_tile(sV, Vb + (size_t)(kb + 1) * 64 * HDIM, tid);
            cp_commit();
        }
    }

    // ---- epilogue: 1/l, write merged-head [B,S,D] ----
    if (lane < 4) {
#pragma unroll
        for (int nf = 0; nf < 2; nf++)
#pragma unroll
            for (int par = 0; par < 2; par++)
                sRed[qw + 8 * nf + 2 * lane + par] = l_i[nf][par];
    }
    __syncwarp();
    const float il0 = 1.f / sRed[qw + g];
    const float il1 = 1.f / sRed[qw + g + 8];

    const int q0 = qb * 128 + qw + g;
    const int q1 = q0 + 8;
    const size_t base0 = ((size_t)b * SEQ + q0) * DMODEL + h * HDIM;
    const size_t base1 = ((size_t)b * SEQ + q1) * DMODEL + h * HDIM;
#pragma unroll
    for (int nf2 = 0; nf2 < 16; nf2++) {
        const int d = 8 * nf2 + 2 * t;
        float2 v0, v1;
        v0.x = acc_o[nf2][0] * il0; v0.y = acc_o[nf2][1] * il0;
        v1.x = acc_o[nf2][2] * il1; v1.y = acc_o[nf2][3] * il1;
        *(float2*)&O[base0 + d] = v0;
        *(float2*)&O[base1 + d] = v1;
    }
}

// ---------------------------------------------------------------------------
// Launch
// ---------------------------------------------------------------------------
extern "C" void kernel_launch(void* const* d_in, const int* in_sizes, int n_in,
                              void* d_out, int out_size)
{
    const float* x  = (const float*)d_in[0];
    const float* Wq = (const float*)d_in[1];
    const float* bq = (const float*)d_in[2];
    const float* Wk = (const float*)d_in[3];
    const float* bk = (const float*)d_in[4];
    const float* Wv = (const float*)d_in[5];
    const float* bv = (const float*)d_in[6];
    const float* Wo = (const float*)d_in[7];
    const float* bo = (const float*)d_in[8];
    float* out = (float*)d_out;

    float *q, *k, *v, *attn;
    cudaGetSymbolAddress((void**)&q,    g_q);
    cudaGetSymbolAddress((void**)&k,    g_k);
    cudaGetSymbolAddress((void**)&v,    g_v);
    cudaGetSymbolAddress((void**)&attn, g_attn);

    cudaFuncSetAttribute(attn_mma_kernel,
                         cudaFuncAttributeMaxDynamicSharedMemorySize, SMA_BYTES);

    dim3 gemm_grid(GN / 128, M_TOK / 128);   // (16, 64)

    gemm_tf32_kernel<<<gemm_grid, 256>>>(x, Wq, bq, q, 1);
    gemm_tf32_kernel<<<gemm_grid, 256>>>(x, Wk, bk, k, 1);
    gemm_tf32_kernel<<<gemm_grid, 256>>>(x, Wv, bv, v, 1);

    attn_mma_kernel<<<dim3(SEQ / 128, NHEADS, BATCH), 256, SMA_BYTES>>>(q, k, v, attn);

    gemm_tf32_kernel<<<gemm_grid, 256>>>(attn, Wo, bo, out, 0);
}